// round 1
// baseline (speedup 1.0000x reference)
#include <cuda_runtime.h>
#include <cstdint>

#define NB 32
#define NT 400
#define ND 2048
#define S_DEN 2000
#define E_DEN 60000
#define S_NUM 512
#define E_NUM 2048

// ---------------- device scratch (no allocations allowed) ----------------
__device__ int g_dcnt[S_DEN];
__device__ int g_dfill[S_DEN];
__device__ int g_drow[S_DEN + 1];
__device__ uint2 g_dedge[E_DEN];
__device__ unsigned short g_dout[E_DEN];
__device__ int g_dscut[5];
__device__ int g_decut[5];

__device__ int g_ncnt[NB * S_NUM];
__device__ int g_nfill[NB * S_NUM];
__device__ int g_nrow[NB * (S_NUM + 1)];
__device__ uint2 g_nedge[NB * E_NUM];
__device__ unsigned short g_nout[NB * E_NUM];
__device__ int g_nscut[NB * 5];
__device__ int g_necut[NB * 5];

__device__ float g_objd[NB];
__device__ float g_objn[NB];

// ---------------- cluster primitives ----------------
__device__ __forceinline__ unsigned cluster_rank() {
    unsigned r;
    asm("mov.u32 %0, %%cluster_ctarank;" : "=r"(r));
    return r;
}
__device__ __forceinline__ void cluster_sync() {
    asm volatile("barrier.cluster.arrive.aligned;" ::: "memory");
    asm volatile("barrier.cluster.wait.aligned;" ::: "memory");
}
__device__ __forceinline__ unsigned mapa_addr(const void* p, int rank) {
    unsigned local = (unsigned)__cvta_generic_to_shared(p);
    unsigned remote;
    asm("mapa.shared::cluster.u32 %0, %1, %2;" : "=r"(remote) : "r"(local), "r"(rank));
    return remote;
}
__device__ __forceinline__ void st_cluster_f32(unsigned addr, float v) {
    asm volatile("st.shared::cluster.f32 [%0], %1;" :: "r"(addr), "f"(v) : "memory");
}

// ---------------- preprocessing ----------------
__global__ void k_zero() {
    int i = blockIdx.x * blockDim.x + threadIdx.x;
    if (i < S_DEN) { g_dcnt[i] = 0; g_dfill[i] = 0; }
    if (i < NB * S_NUM) { g_ncnt[i] = 0; g_nfill[i] = 0; }
}

__global__ void k_hist(const int* __restrict__ de_out, const int* __restrict__ ne_out) {
    int i = blockIdx.x * blockDim.x + threadIdx.x;
    if (i < E_DEN) atomicAdd(&g_dcnt[de_out[i]], 1);
    if (i < NB * E_NUM) {
        int b = i >> 11;  // E_NUM = 2048
        atomicAdd(&g_ncnt[b * S_NUM + ne_out[i]], 1);
    }
}

__global__ void k_scan_den() {
    __shared__ int p[1024];
    int tid = threadIdx.x;
    int i0 = 2 * tid, i1 = 2 * tid + 1;
    int c0 = (i0 < S_DEN) ? g_dcnt[i0] : 0;
    int c1 = (i1 < S_DEN) ? g_dcnt[i1] : 0;
    int partial = c0 + c1;
    p[tid] = partial;
    __syncthreads();
    for (int off = 1; off < 1024; off <<= 1) {
        int v = p[tid];
        if (tid >= off) v += p[tid - off];
        __syncthreads();
        p[tid] = v;
        __syncthreads();
    }
    int base = p[tid] - partial;  // exclusive prefix at i0
    if (i0 <= S_DEN) g_drow[i0] = base;
    if (i1 <= S_DEN) g_drow[i1] = base + c0;
    if (tid == 0) g_drow[S_DEN] = E_DEN;
    __syncthreads();
    // state-aligned quartile cuts
    for (int s = tid; s < S_DEN; s += 1024) {
        int r = g_drow[s];
        int rp = (s == 0) ? -1 : g_drow[s - 1];
        #pragma unroll
        for (int k = 1; k < 4; k++) {
            int target = k * (E_DEN / 4);
            if (r >= target && rp < target) { g_dscut[k] = s; g_decut[k] = r; }
        }
    }
    if (tid == 0) { g_dscut[0] = 0; g_decut[0] = 0; g_dscut[4] = S_DEN; g_decut[4] = E_DEN; }
}

__global__ void k_scan_num() {
    __shared__ int p[S_NUM];
    int b = blockIdx.x, tid = threadIdx.x;
    int c = g_ncnt[b * S_NUM + tid];
    p[tid] = c;
    __syncthreads();
    for (int off = 1; off < S_NUM; off <<= 1) {
        int v = p[tid];
        if (tid >= off) v += p[tid - off];
        __syncthreads();
        p[tid] = v;
        __syncthreads();
    }
    int incl = p[tid];
    int base = incl - c;
    g_nrow[b * (S_NUM + 1) + tid] = base;
    if (tid == S_NUM - 1) g_nrow[b * (S_NUM + 1) + S_NUM] = incl;
    __syncthreads();
    p[tid] = base;  // exclusive prefix in smem for cut search
    __syncthreads();
    #pragma unroll
    for (int k = 1; k < 4; k++) {
        int target = k * (E_NUM / 4);
        if (base >= target && (tid == 0 || p[tid - 1] < target)) {
            g_nscut[b * 5 + k] = tid;
            g_necut[b * 5 + k] = base;
        }
    }
    if (tid == 0) {
        g_nscut[b * 5] = 0; g_necut[b * 5] = 0;
        g_nscut[b * 5 + 4] = S_NUM; g_necut[b * 5 + 4] = E_NUM;
    }
}

__global__ void k_scatter(const int* __restrict__ de_in, const int* __restrict__ de_out,
                          const int* __restrict__ de_pdf, const float* __restrict__ de_prob,
                          const int* __restrict__ ne_in, const int* __restrict__ ne_out,
                          const int* __restrict__ ne_pdf, const float* __restrict__ ne_prob) {
    int i = blockIdx.x * blockDim.x + threadIdx.x;
    if (i < E_DEN) {
        int out = de_out[i];
        int p = atomicAdd(&g_dfill[out], 1);
        int pos = g_drow[out] + p;
        unsigned flag = (pos + 1 == g_drow[out + 1]) ? 1u : 0u;
        unsigned pack = (unsigned)de_in[i] | ((unsigned)de_pdf[i] << 11) | (flag << 22);
        g_dedge[pos] = make_uint2(pack, __float_as_uint(de_prob[i]));
        g_dout[pos] = (unsigned short)out;
    }
    if (i < NB * E_NUM) {
        int b = i >> 11;
        int out = ne_out[i];
        int p = atomicAdd(&g_nfill[b * S_NUM + out], 1);
        int pos = g_nrow[b * (S_NUM + 1) + out] + p;
        unsigned flag = (pos + 1 == g_nrow[b * (S_NUM + 1) + out + 1]) ? 1u : 0u;
        unsigned pack = (unsigned)ne_in[i] | ((unsigned)ne_pdf[i] << 11) | (flag << 22);
        g_nedge[b * E_NUM + pos] = make_uint2(pack, __float_as_uint(ne_prob[i]));
        g_nout[b * E_NUM + pos] = (unsigned short)out;
    }
}

// ---------------- main recursion: 1 cluster (4 CTAs) per utterance ----------------
__global__ void __cluster_dims__(4, 1, 1) __launch_bounds__(1024, 1)
k_main(const float* __restrict__ x, const int* __restrict__ xlen,
       const float* __restrict__ dleaky, const float* __restrict__ dfinal,
       const float* __restrict__ nleaky, const float* __restrict__ nfinal) {
    const int rank = (int)cluster_rank();
    const int b = (int)(blockIdx.x >> 2);
    const int tid = threadIdx.x;

    __shared__ float s_alpha_d[S_DEN];
    __shared__ float s_anew_d[S_DEN];
    __shared__ float s_cleak_d[S_DEN];
    __shared__ __align__(16) float s_xt[ND];
    __shared__ float s_alpha_n[S_NUM];
    __shared__ float s_anew_n[S_NUM];
    __shared__ float s_cleak_n[S_NUM];
    __shared__ float s_mail_d[4];
    __shared__ float s_mail_n[4];
    __shared__ float s_red[2];
    __shared__ float s_fin[2];

    for (int s = tid; s < S_DEN; s += 1024) {
        float c = 1e-5f * dleaky[s];
        s_cleak_d[s] = c;
        s_alpha_d[s] = c + (s == 0 ? 1.0f : 0.0f);
        s_anew_d[s] = 0.0f;
    }
    for (int s = tid; s < S_NUM; s += 1024) {
        float c = 1e-20f * nleaky[b * S_NUM + s];
        s_cleak_n[s] = c;
        s_alpha_n[s] = c + (s == 0 ? 1.0f : 0.0f);
        s_anew_n[s] = 0.0f;
    }

    const int de0 = g_decut[rank], de1 = g_decut[rank + 1];
    const int ds0 = g_dscut[rank], ds1 = g_dscut[rank + 1];
    const int ne0 = g_necut[b * 5 + rank], ne1 = g_necut[b * 5 + rank + 1];
    const int ns0 = g_nscut[b * 5 + rank], ns1 = g_nscut[b * 5 + rank + 1];

    const uint2* __restrict__ nedge = g_nedge + b * E_NUM;
    const unsigned short* __restrict__ nout = g_nout + b * E_NUM;

    unsigned ad[4], an[4], md[4], mn[4];
    #pragma unroll
    for (int k = 0; k < 4; k++) {
        ad[k] = mapa_addr(s_alpha_d, k);
        an[k] = mapa_addr(s_alpha_n, k);
        md[k] = mapa_addr(s_mail_d, k);
        mn[k] = mapa_addr(s_mail_n, k);
    }

    const int len = xlen[b];
    const float* xb = x + (size_t)b * NT * ND;

    float lzd = 0.0f, lzn = 0.0f;

    cluster_sync();

    for (int t = 0; t < len; ++t) {
        // exp'd clamped network output for this frame -> smem
        const float4* xr = (const float4*)(xb + (size_t)t * ND);
        for (int i = tid; i < ND / 4; i += 1024) {
            float4 v = __ldg(xr + i);
            float4 o;
            o.x = __expf(fminf(fmaxf(v.x, -30.f), 30.f));
            o.y = __expf(fminf(fmaxf(v.y, -30.f), 30.f));
            o.z = __expf(fminf(fmaxf(v.z, -30.f), 30.f));
            o.w = __expf(fminf(fmaxf(v.w, -30.f), 30.f));
            ((float4*)s_xt)[i] = o;
        }
        if (tid < 2) s_red[tid] = 0.0f;
        __syncthreads();

        float ssum = 0.0f, nsum = 0.0f;
        // ---- den edges (CSR by dest, state-aligned slice for this rank) ----
        {
            int n = de1 - de0;
            int per = (n + 1023) >> 10;
            int e = de0 + tid * per;
            int eend = min(e + per, de1);
            if (e < eend) {
                int cur = g_dout[e];
                float acc = 0.0f;
                #pragma unroll 4
                for (; e < eend; ++e) {
                    uint2 w = __ldg(&g_dedge[e]);
                    float a = s_alpha_d[w.x & 2047u];
                    float xv = s_xt[(w.x >> 11) & 2047u];
                    acc = fmaf(a * xv, __uint_as_float(w.y), acc);
                    if (w.x & (1u << 22)) {
                        atomicAdd(&s_anew_d[cur], acc);
                        ssum += acc;
                        acc = 0.0f;
                        if (e + 1 < eend) cur = g_dout[e + 1];
                    }
                }
                if (acc != 0.0f) { atomicAdd(&s_anew_d[cur], acc); ssum += acc; }
            }
        }
        // ---- num edges ----
        {
            int n = ne1 - ne0;
            int per = (n + 1023) >> 10;
            int e = ne0 + tid * per;
            int eend = min(e + per, ne1);
            if (e < eend) {
                int cur = nout[e];
                float acc = 0.0f;
                for (; e < eend; ++e) {
                    uint2 w = __ldg(&nedge[e]);
                    float a = s_alpha_n[w.x & 2047u];
                    float xv = s_xt[(w.x >> 11) & 2047u];
                    acc = fmaf(a * xv, __uint_as_float(w.y), acc);
                    if (w.x & (1u << 22)) {
                        atomicAdd(&s_anew_n[cur], acc);
                        nsum += acc;
                        acc = 0.0f;
                        if (e + 1 < eend) cur = nout[e + 1];
                    }
                }
                if (acc != 0.0f) { atomicAdd(&s_anew_n[cur], acc); nsum += acc; }
            }
        }
        // per-CTA partial asum = sum of flushed accumulators
        #pragma unroll
        for (int o = 16; o; o >>= 1) {
            ssum += __shfl_xor_sync(0xffffffffu, ssum, o);
            nsum += __shfl_xor_sync(0xffffffffu, nsum, o);
        }
        if ((tid & 31) == 0) {
            atomicAdd(&s_red[0], ssum);
            atomicAdd(&s_red[1], nsum);
        }
        __syncthreads();
        if (tid == 0) {
            float rs = s_red[0], rn = s_red[1];
            #pragma unroll
            for (int k = 0; k < 4; k++) {
                st_cluster_f32(md[k] + 4u * rank, rs);
                st_cluster_f32(mn[k] + 4u * rank, rn);
            }
        }
        cluster_sync();

        float asd = s_mail_d[0] + s_mail_d[1] + s_mail_d[2] + s_mail_d[3];
        float asn = s_mail_n[0] + s_mail_n[1] + s_mail_n[2] + s_mail_n[3];
        float invd = 1.0f / asd;
        float invn = 1.0f / asn;

        // adash = anew/asum + coeff*leaky ; broadcast owned slice to all 4 CTAs
        for (int s = ds0 + tid; s < ds1; s += 1024) {
            float a = s_anew_d[s];
            s_anew_d[s] = 0.0f;
            float v = fmaf(a, invd, s_cleak_d[s]);
            #pragma unroll
            for (int k = 0; k < 4; k++) st_cluster_f32(ad[k] + 4u * (unsigned)s, v);
        }
        for (int s = ns0 + tid; s < ns1; s += 1024) {
            float a = s_anew_n[s];
            s_anew_n[s] = 0.0f;
            float v = fmaf(a, invn, s_cleak_n[s]);
            #pragma unroll
            for (int k = 0; k < 4; k++) st_cluster_f32(an[k] + 4u * (unsigned)s, v);
        }
        if (rank == 0 && tid == 0) { lzd += logf(asd); lzn += logf(asn); }
        cluster_sync();
    }

    // final: objf_b = logz + log(sum(alpha*final)) ; rank 0 holds full alpha replica
    if (rank == 0) {
        if (tid < 2) s_fin[tid] = 0.0f;
        __syncthreads();
        float fd = 0.0f, fn = 0.0f;
        for (int s = tid; s < S_DEN; s += 1024) fd += s_alpha_d[s] * __ldg(&dfinal[s]);
        for (int s = tid; s < S_NUM; s += 1024) fn += s_alpha_n[s] * __ldg(&nfinal[b * S_NUM + s]);
        #pragma unroll
        for (int o = 16; o; o >>= 1) {
            fd += __shfl_xor_sync(0xffffffffu, fd, o);
            fn += __shfl_xor_sync(0xffffffffu, fn, o);
        }
        if ((tid & 31) == 0) { atomicAdd(&s_fin[0], fd); atomicAdd(&s_fin[1], fn); }
        __syncthreads();
        if (tid == 0) {
            g_objd[b] = lzd + logf(s_fin[0]);
            g_objn[b] = lzn + logf(s_fin[1]);
        }
    }
}

__global__ void k_final(const int* __restrict__ xlen, float* __restrict__ out) {
    int tid = threadIdx.x;  // 32 threads
    float d = g_objd[tid];
    float n = g_objn[tid];
    float l = (float)xlen[tid];
    #pragma unroll
    for (int o = 16; o; o >>= 1) {
        d += __shfl_xor_sync(0xffffffffu, d, o);
        n += __shfl_xor_sync(0xffffffffu, n, o);
        l += __shfl_xor_sync(0xffffffffu, l, o);
    }
    if (tid == 0) out[0] = -(n - d) / l;
}

// ---------------- launch ----------------
extern "C" void kernel_launch(void* const* d_in, const int* in_sizes, int n_in,
                              void* d_out, int out_size) {
    const float* x = (const float*)d_in[0];
    const int* xlen = (const int*)d_in[1];
    const int* de_in = (const int*)d_in[2];
    const int* de_out = (const int*)d_in[3];
    const int* de_pdf = (const int*)d_in[4];
    const float* de_prob = (const float*)d_in[5];
    const float* dleaky = (const float*)d_in[6];
    const float* dfinal = (const float*)d_in[7];
    const int* ne_in = (const int*)d_in[8];
    const int* ne_out = (const int*)d_in[9];
    const int* ne_pdf = (const int*)d_in[10];
    const float* ne_prob = (const float*)d_in[11];
    const float* nleaky = (const float*)d_in[12];
    const float* nfinal = (const float*)d_in[13];
    float* out = (float*)d_out;

    k_zero<<<64, 256>>>();
    k_hist<<<256, 256>>>(de_out, ne_out);
    k_scan_den<<<1, 1024>>>();
    k_scan_num<<<NB, 512>>>();
    k_scatter<<<256, 256>>>(de_in, de_out, de_pdf, de_prob, ne_in, ne_out, ne_pdf, ne_prob);
    k_main<<<NB * 4, 1024>>>(x, xlen, dleaky, dfinal, nleaky, nfinal);
    k_final<<<1, 32>>>(xlen, out);
}

// round 3
// speedup vs baseline: 1.3461x; 1.3461x over previous
#include <cuda_runtime.h>
#include <cstdint>

#define NB 32
#define NT 400
#define ND 2048
#define S_DEN 2000
#define E_DEN 60000
#define S_NUM 512
#define E_NUM 2048
#define DCAP 15360
#define NCAP 768

// ---- dynamic smem layout (bytes) ----
#define OFF_ALPHA_D 0            // float[2][S_DEN]   16000
#define OFF_ANEW_D  16000        // float[S_DEN]       8000
#define OFF_CLEAK_D 24000        // float[S_DEN]       8000
#define OFF_XT      32000        // float[2][ND]      16384
#define OFF_ALPHA_N 48384        // float[2][S_NUM]    4096
#define OFF_ANEW_N  52480        // float[S_NUM]       2048
#define OFF_CLEAK_N 54528        // float[S_NUM]       2048
#define OFF_NEDGE   56576        // uint2[NCAP]        6144
#define OFF_NDOUT   62720        // u16[NCAP]          1536
#define OFF_MAIL_D  64256        // u64[4]               32
#define OFF_MAIL_N  64288        // u64[4]               32
#define OFF_RED     64320        // float[4]             16
#define OFF_SCAL    64336        // float[4]             16
#define OFF_DEDGE   64384        // uint2[DCAP]      122880
#define OFF_DDOUT   187264       // u16[DCAP]         30720
#define SMEM_MAIN   217984

// ---------------- device scratch ----------------
__device__ int g_dcnt[S_DEN];
__device__ int g_dfill[S_DEN];
__device__ int g_drow[S_DEN + 1];
__device__ uint2 g_dedge[E_DEN];
__device__ unsigned short g_dout[E_DEN];
__device__ int g_dscut[5];
__device__ int g_decut[5];

__device__ int g_ncnt[NB * S_NUM];
__device__ int g_nfill[NB * S_NUM];
__device__ int g_nrow[NB * (S_NUM + 1)];
__device__ uint2 g_nedge[NB * E_NUM];
__device__ unsigned short g_nout[NB * E_NUM];
__device__ int g_nscut[NB * 5];
__device__ int g_necut[NB * 5];

__device__ float g_objd[NB];
__device__ float g_objn[NB];

__device__ float g_xexp[(size_t)NB * NT * ND];   // pre-exp'd network outputs

// ---------------- cluster / async primitives ----------------
__device__ __forceinline__ unsigned cluster_rank() {
    unsigned r;
    asm("mov.u32 %0, %%cluster_ctarank;" : "=r"(r));
    return r;
}
__device__ __forceinline__ void cluster_sync() {
    asm volatile("barrier.cluster.arrive.aligned;" ::: "memory");
    asm volatile("barrier.cluster.wait.aligned;" ::: "memory");
}
__device__ __forceinline__ unsigned mapa_addr(const void* p, int rank) {
    unsigned local = (unsigned)__cvta_generic_to_shared(p);
    unsigned remote;
    asm("mapa.shared::cluster.u32 %0, %1, %2;" : "=r"(remote) : "r"(local), "r"(rank));
    return remote;
}
__device__ __forceinline__ void stc_f32(unsigned addr, float v) {
    asm volatile("st.shared::cluster.f32 [%0], %1;" :: "r"(addr), "f"(v) : "memory");
}
__device__ __forceinline__ void stc_u64(unsigned addr, unsigned long long v) {
    asm volatile("st.shared::cluster.u64 [%0], %1;" :: "r"(addr), "l"(v) : "memory");
}
__device__ __forceinline__ unsigned long long ldv_u64(const void* p) {
    unsigned long long v;
    asm volatile("ld.volatile.shared.u64 %0, [%1];"
                 : "=l"(v) : "r"((unsigned)__cvta_generic_to_shared(p)));
    return v;
}
__device__ __forceinline__ void cpa16(void* dst, const void* src) {
    unsigned d = (unsigned)__cvta_generic_to_shared(dst);
    asm volatile("cp.async.cg.shared.global [%0], [%1], 16;" :: "r"(d), "l"(src));
}

// ---------------- preprocessing ----------------
__global__ void k_exp(const float* __restrict__ x) {
    size_t i = (size_t)blockIdx.x * blockDim.x + threadIdx.x;   // float4 index
    float4 v = __ldg(((const float4*)x) + i);
    float4 o;
    o.x = __expf(fminf(fmaxf(v.x, -30.f), 30.f));
    o.y = __expf(fminf(fmaxf(v.y, -30.f), 30.f));
    o.z = __expf(fminf(fmaxf(v.z, -30.f), 30.f));
    o.w = __expf(fminf(fmaxf(v.w, -30.f), 30.f));
    ((float4*)g_xexp)[i] = o;
}

__global__ void k_zero() {
    int i = blockIdx.x * blockDim.x + threadIdx.x;
    if (i < S_DEN) { g_dcnt[i] = 0; g_dfill[i] = 0; }
    if (i < NB * S_NUM) { g_ncnt[i] = 0; g_nfill[i] = 0; }
}

__global__ void k_hist(const int* __restrict__ de_out, const int* __restrict__ ne_out) {
    int i = blockIdx.x * blockDim.x + threadIdx.x;
    if (i < E_DEN) atomicAdd(&g_dcnt[de_out[i]], 1);
    if (i < NB * E_NUM) {
        int b = i >> 11;
        atomicAdd(&g_ncnt[b * S_NUM + ne_out[i]], 1);
    }
}

__global__ void k_scan_den() {
    __shared__ int p[1024];
    int tid = threadIdx.x;
    int i0 = 2 * tid, i1 = 2 * tid + 1;
    int c0 = (i0 < S_DEN) ? g_dcnt[i0] : 0;
    int c1 = (i1 < S_DEN) ? g_dcnt[i1] : 0;
    int partial = c0 + c1;
    p[tid] = partial;
    __syncthreads();
    for (int off = 1; off < 1024; off <<= 1) {
        int v = p[tid];
        if (tid >= off) v += p[tid - off];
        __syncthreads();
        p[tid] = v;
        __syncthreads();
    }
    int base = p[tid] - partial;
    if (i0 <= S_DEN) g_drow[i0] = base;
    if (i1 <= S_DEN) g_drow[i1] = base + c0;
    if (tid == 0) g_drow[S_DEN] = E_DEN;
    __syncthreads();
    for (int s = tid; s < S_DEN; s += 1024) {
        int r = g_drow[s];
        int rp = (s == 0) ? -1 : g_drow[s - 1];
        #pragma unroll
        for (int k = 1; k < 4; k++) {
            int target = k * (E_DEN / 4);
            if (r >= target && rp < target) { g_dscut[k] = s; g_decut[k] = r; }
        }
    }
    if (tid == 0) { g_dscut[0] = 0; g_decut[0] = 0; g_dscut[4] = S_DEN; g_decut[4] = E_DEN; }
}

__global__ void k_scan_num() {
    __shared__ int p[S_NUM];
    int b = blockIdx.x, tid = threadIdx.x;
    int c = g_ncnt[b * S_NUM + tid];
    p[tid] = c;
    __syncthreads();
    for (int off = 1; off < S_NUM; off <<= 1) {
        int v = p[tid];
        if (tid >= off) v += p[tid - off];
        __syncthreads();
        p[tid] = v;
        __syncthreads();
    }
    int incl = p[tid];
    int base = incl - c;
    g_nrow[b * (S_NUM + 1) + tid] = base;
    if (tid == S_NUM - 1) g_nrow[b * (S_NUM + 1) + S_NUM] = incl;
    __syncthreads();
    p[tid] = base;
    __syncthreads();
    #pragma unroll
    for (int k = 1; k < 4; k++) {
        int target = k * (E_NUM / 4);
        if (base >= target && (tid == 0 || p[tid - 1] < target)) {
            g_nscut[b * 5 + k] = tid;
            g_necut[b * 5 + k] = base;
        }
    }
    if (tid == 0) {
        g_nscut[b * 5] = 0; g_necut[b * 5] = 0;
        g_nscut[b * 5 + 4] = S_NUM; g_necut[b * 5 + 4] = E_NUM;
    }
}

__global__ void k_scatter(const int* __restrict__ de_in, const int* __restrict__ de_out,
                          const int* __restrict__ de_pdf, const float* __restrict__ de_prob,
                          const int* __restrict__ ne_in, const int* __restrict__ ne_out,
                          const int* __restrict__ ne_pdf, const float* __restrict__ ne_prob) {
    int i = blockIdx.x * blockDim.x + threadIdx.x;
    if (i < E_DEN) {
        int out = de_out[i];
        int p = atomicAdd(&g_dfill[out], 1);
        int pos = g_drow[out] + p;
        unsigned flag = (pos + 1 == g_drow[out + 1]) ? 1u : 0u;
        unsigned pack = (unsigned)de_in[i] | ((unsigned)de_pdf[i] << 11) | (flag << 22);
        g_dedge[pos] = make_uint2(pack, __float_as_uint(de_prob[i]));
        g_dout[pos] = (unsigned short)out;
    }
    if (i < NB * E_NUM) {
        int b = i >> 11;
        int out = ne_out[i];
        int p = atomicAdd(&g_nfill[b * S_NUM + out], 1);
        int pos = g_nrow[b * (S_NUM + 1) + out] + p;
        unsigned flag = (pos + 1 == g_nrow[b * (S_NUM + 1) + out + 1]) ? 1u : 0u;
        unsigned pack = (unsigned)ne_in[i] | ((unsigned)ne_pdf[i] << 11) | (flag << 22);
        g_nedge[b * E_NUM + pos] = make_uint2(pack, __float_as_uint(ne_prob[i]));
        g_nout[b * E_NUM + pos] = (unsigned short)out;
    }
}

// ---------------- main recursion: 1 cluster (4 CTAs) per utterance ----------------
__global__ void __cluster_dims__(4, 1, 1) __launch_bounds__(1024, 1)
k_main(const int* __restrict__ xlen,
       const float* __restrict__ dleaky, const float* __restrict__ dfinal,
       const float* __restrict__ nleaky, const float* __restrict__ nfinal) {
    extern __shared__ char sm[];
    float* AD  = (float*)(sm + OFF_ALPHA_D);   // [2][S_DEN]
    float* AW  = (float*)(sm + OFF_ANEW_D);    // [S_DEN]
    float* CLD = (float*)(sm + OFF_CLEAK_D);
    float* XT  = (float*)(sm + OFF_XT);        // [2][ND]
    float* AN  = (float*)(sm + OFF_ALPHA_N);   // [2][S_NUM]
    float* AWN = (float*)(sm + OFF_ANEW_N);
    float* CLN = (float*)(sm + OFF_CLEAK_N);
    uint2* NE  = (uint2*)(sm + OFF_NEDGE);
    unsigned short* NO = (unsigned short*)(sm + OFF_NDOUT);
    unsigned long long* MD = (unsigned long long*)(sm + OFF_MAIL_D);
    unsigned long long* MN = (unsigned long long*)(sm + OFF_MAIL_N);
    float* RED = (float*)(sm + OFF_RED);
    float* SC  = (float*)(sm + OFF_SCAL);
    uint2* DE  = (uint2*)(sm + OFF_DEDGE);
    unsigned short* DD = (unsigned short*)(sm + OFF_DDOUT);

    const int rank = (int)cluster_rank();
    const int b = (int)(blockIdx.x >> 2);
    const int tid = threadIdx.x;

    // ---- init smem state ----
    for (int s = tid; s < S_DEN; s += 1024) {
        float c = 1e-5f * __ldg(dleaky + s);
        CLD[s] = c;
        AD[s] = c + (s == 0 ? 1.0f : 0.0f);
        AW[s] = 0.0f;
    }
    for (int s = tid; s < S_NUM; s += 1024) {
        float c = 1e-20f * __ldg(nleaky + b * S_NUM + s);
        CLN[s] = c;
        AN[s] = c + (s == 0 ? 1.0f : 0.0f);
        AWN[s] = 0.0f;
    }
    if (tid < 4) { MD[tid] = 0ull; MN[tid] = 0ull; RED[tid] = 0.0f; }

    const int de0 = g_decut[rank], de1 = g_decut[rank + 1];
    const int ds0 = g_dscut[rank], ds1 = g_dscut[rank + 1];
    const int ne0 = g_necut[b * 5 + rank], ne1 = g_necut[b * 5 + rank + 1];
    const int ns0 = g_nscut[b * 5 + rank], ns1 = g_nscut[b * 5 + rank + 1];

    // ---- copy edge slices to smem (transposed: thread t's k-th edge at k*1024+t) ----
    const int dn = de1 - de0;
    const int dper = (dn + 1023) >> 10;
    for (int k = 0; k < dper; k++) {
        int j = tid * dper + k;
        if (j < dn) {
            DE[k * 1024 + tid] = __ldg(&g_dedge[de0 + j]);
            DD[k * 1024 + tid] = __ldg(&g_dout[de0 + j]);
        }
    }
    const int nn = ne1 - ne0;
    const int nper = (nn + 1023) >> 10;
    for (int k = 0; k < nper; k++) {
        int j = tid * nper + k;
        if (j < nn) {
            NE[k * 1024 + tid] = __ldg(&g_nedge[(size_t)b * E_NUM + ne0 + j]);
            NO[k * 1024 + tid] = __ldg(&g_nout[(size_t)b * E_NUM + ne0 + j]);
        }
    }

    // remote smem base addresses
    unsigned ad[4], an[4], md[4], mn[4];
    #pragma unroll
    for (int k = 0; k < 4; k++) {
        ad[k] = mapa_addr(AD, k);
        an[k] = mapa_addr(AN, k);
        md[k] = mapa_addr(MD, k);
        mn[k] = mapa_addr(MN, k);
    }

    const int len = xlen[b];
    const float* xe = g_xexp + (size_t)b * NT * ND;

    // prefetch frame 0
    if (tid < 512) cpa16(XT + tid * 4, xe + tid * 4);
    asm volatile("cp.async.commit_group;" ::: "memory");

    float lzd = 0.0f, lzn = 0.0f;

    __syncthreads();
    cluster_sync();   // everyone's mails/alpha initialized before any traffic

    const int dbase = tid * dper;
    const int nbase = tid * nper;

    for (int t = 0; t < len; ++t) {
        const int buf = t & 1, nbuf = buf ^ 1;

        // prefetch next frame into the other buffer
        if (t + 1 < len && tid < 512)
            cpa16(XT + nbuf * ND + tid * 4, xe + (size_t)(t + 1) * ND + tid * 4);
        asm volatile("cp.async.commit_group;" ::: "memory");
        asm volatile("cp.async.wait_group 1;" ::: "memory");   // frame t's data resident
        __syncthreads();

        const float* xtb = XT + buf * ND;
        const float* ab  = AD + buf * S_DEN;
        const float* abn = AN + buf * S_NUM;

        float ssum = 0.0f, nsum = 0.0f;

        // ---- den edges (all from smem) ----
        if (dbase < dn) {
            float acc = 0.0f;
            const int kend = min(dper, dn - dbase);
            #pragma unroll 5
            for (int k = 0; k < kend; k++) {
                uint2 w = DE[k * 1024 + tid];
                float a = ab[w.x & 2047u];
                float xv = xtb[(w.x >> 11) & 2047u];
                acc = fmaf(a * xv, __uint_as_float(w.y), acc);
                if (w.x & (1u << 22)) {
                    atomicAdd(&AW[DD[k * 1024 + tid]], acc);
                    ssum += acc;
                    acc = 0.0f;
                }
            }
            if (acc != 0.0f) {
                atomicAdd(&AW[DD[(kend - 1) * 1024 + tid]], acc);
                ssum += acc;
            }
        }
        // ---- num edges ----
        if (nbase < nn) {
            float acc = 0.0f;
            const int kend = min(nper, nn - nbase);
            for (int k = 0; k < kend; k++) {
                uint2 w = NE[k * 1024 + tid];
                float a = abn[w.x & 2047u];
                float xv = xtb[(w.x >> 11) & 2047u];
                acc = fmaf(a * xv, __uint_as_float(w.y), acc);
                if (w.x & (1u << 22)) {
                    atomicAdd(&AWN[NO[k * 1024 + tid]], acc);
                    nsum += acc;
                    acc = 0.0f;
                }
            }
            if (acc != 0.0f) {
                atomicAdd(&AWN[NO[(kend - 1) * 1024 + tid]], acc);
                nsum += acc;
            }
        }

        // ---- per-CTA partial sums ----
        #pragma unroll
        for (int o = 16; o; o >>= 1) {
            ssum += __shfl_xor_sync(0xffffffffu, ssum, o);
            nsum += __shfl_xor_sync(0xffffffffu, nsum, o);
        }
        if ((tid & 31) == 0) {
            atomicAdd(&RED[0], ssum);
            atomicAdd(&RED[1], nsum);
        }
        __syncthreads();

        // ---- mailbox exchange (single-copy-atomic u64: value | counter) ----
        if (tid == 0) {
            unsigned long long ctr = ((unsigned long long)(unsigned)(t + 1)) << 32;
            unsigned long long pd = ctr | (unsigned long long)__float_as_uint(RED[0]);
            unsigned long long pn = ctr | (unsigned long long)__float_as_uint(RED[1]);
            #pragma unroll
            for (int k = 0; k < 4; k++) {
                stc_u64(md[k] + 8u * (unsigned)rank, pd);
                stc_u64(mn[k] + 8u * (unsigned)rank, pn);
            }
            float asd = 0.0f, asn = 0.0f;
            #pragma unroll
            for (int k = 0; k < 4; k++) {
                unsigned long long u;
                do { u = ldv_u64(&MD[k]); } while ((unsigned)(u >> 32) != (unsigned)(t + 1));
                asd += __uint_as_float((unsigned)u);
                do { u = ldv_u64(&MN[k]); } while ((unsigned)(u >> 32) != (unsigned)(t + 1));
                asn += __uint_as_float((unsigned)u);
            }
            SC[0] = 1.0f / asd;
            SC[1] = 1.0f / asn;
            if (rank == 0) { lzd += logf(asd); lzn += logf(asn); }
        }
        __syncthreads();

        // ---- normalize + leaky, broadcast owned slice into alpha[buf^1] of all ranks ----
        const float invd = SC[0], invn = SC[1];
        for (int s = ds0 + tid; s < ds1; s += 1024) {
            float a = AW[s];
            AW[s] = 0.0f;
            float v = fmaf(a, invd, CLD[s]);
            unsigned off = 4u * (unsigned)(nbuf * S_DEN + s);
            #pragma unroll
            for (int k = 0; k < 4; k++) stc_f32(ad[k] + off, v);
        }
        for (int s = ns0 + tid; s < ns1; s += 1024) {
            float a = AWN[s];
            AWN[s] = 0.0f;
            float v = fmaf(a, invn, CLN[s]);
            unsigned off = 4u * (unsigned)(nbuf * S_NUM + s);
            #pragma unroll
            for (int k = 0; k < 4; k++) stc_f32(an[k] + off, v);
        }
        if (tid < 2) RED[tid] = 0.0f;   // reset for next frame (consumed pre-sync above)
        cluster_sync();
    }

    // ---- final: objf_b = logz + log(sum(alpha * final)) on rank 0 (full replica) ----
    if (rank == 0) {
        if (tid < 2) RED[tid] = 0.0f;
        __syncthreads();
        const int buf = len & 1;
        float fd = 0.0f, fn = 0.0f;
        for (int s = tid; s < S_DEN; s += 1024) fd += AD[buf * S_DEN + s] * __ldg(dfinal + s);
        for (int s = tid; s < S_NUM; s += 1024) fn += AN[buf * S_NUM + s] * __ldg(nfinal + b * S_NUM + s);
        #pragma unroll
        for (int o = 16; o; o >>= 1) {
            fd += __shfl_xor_sync(0xffffffffu, fd, o);
            fn += __shfl_xor_sync(0xffffffffu, fn, o);
        }
        if ((tid & 31) == 0) { atomicAdd(&RED[0], fd); atomicAdd(&RED[1], fn); }
        __syncthreads();
        if (tid == 0) {
            g_objd[b] = lzd + logf(RED[0]);
            g_objn[b] = lzn + logf(RED[1]);
        }
    }
}

__global__ void k_final(const int* __restrict__ xlen, float* __restrict__ out) {
    int tid = threadIdx.x;  // 32 threads
    float d = g_objd[tid];
    float n = g_objn[tid];
    float l = (float)xlen[tid];
    #pragma unroll
    for (int o = 16; o; o >>= 1) {
        d += __shfl_xor_sync(0xffffffffu, d, o);
        n += __shfl_xor_sync(0xffffffffu, n, o);
        l += __shfl_xor_sync(0xffffffffu, l, o);
    }
    if (tid == 0) out[0] = -(n - d) / l;
}

// ---------------- launch ----------------
extern "C" void kernel_launch(void* const* d_in, const int* in_sizes, int n_in,
                              void* d_out, int out_size) {
    const float* x = (const float*)d_in[0];
    const int* xlen = (const int*)d_in[1];
    const int* de_in = (const int*)d_in[2];
    const int* de_out = (const int*)d_in[3];
    const int* de_pdf = (const int*)d_in[4];
    const float* de_prob = (const float*)d_in[5];
    const float* dleaky = (const float*)d_in[6];
    const float* dfinal = (const float*)d_in[7];
    const int* ne_in = (const int*)d_in[8];
    const int* ne_out = (const int*)d_in[9];
    const int* ne_pdf = (const int*)d_in[10];
    const float* ne_prob = (const float*)d_in[11];
    const float* nleaky = (const float*)d_in[12];
    const float* nfinal = (const float*)d_in[13];
    float* out = (float*)d_out;

    cudaFuncSetAttribute(k_main, cudaFuncAttributeMaxDynamicSharedMemorySize, SMEM_MAIN);

    k_exp<<<(NB * NT * ND / 4 + 1023) / 1024, 1024>>>(x);
    k_zero<<<64, 256>>>();
    k_hist<<<256, 256>>>(de_out, ne_out);
    k_scan_den<<<1, 1024>>>();
    k_scan_num<<<NB, 512>>>();
    k_scatter<<<256, 256>>>(de_in, de_out, de_pdf, de_prob, ne_in, ne_out, ne_pdf, ne_prob);
    k_main<<<NB * 4, 1024, SMEM_MAIN>>>(xlen, dleaky, dfinal, nleaky, nfinal);
    k_final<<<1, 32>>>(xlen, out);
}

// round 4
// speedup vs baseline: 1.6057x; 1.1928x over previous
#include <cuda_runtime.h>
#include <cstdint>

#define NB 32
#define NT 400
#define ND 2048
#define S_DEN 2000
#define E_DEN 60000
#define S_NUM 512
#define E_NUM 2048
#define DPER 15
#define NPER 2

// ---- dynamic smem layout (bytes) ----
#define OFF_AD    0        // float[2][S_DEN]        16000
#define OFF_CLD   16000    // float[S_DEN]            8000
#define OFF_XT    24000    // float[2][ND]           16384  (16B aligned)
#define OFF_AN    40384    // float[2][S_NUM]         4096
#define OFF_CLN   44480    // float[S_NUM]            2048
#define OFF_AW    46528    // float[S_DEN]            8000
#define OFF_AWN   54528    // float[S_NUM]            2048
#define OFF_NE    56576    // uint2[NPER*1024]       16384
#define OFF_ND    72960    // u16[NPER*1024]          4096
#define OFF_SRD   77056    // float[32]                128
#define OFF_SRN   77184    // float[32]                128
#define OFF_MAILD 77312    // float[2][4]               32
#define OFF_MAILN 77344    // float[2][4]               32
#define OFF_DPR   77376    // float[DPER*1024]       61440
#define OFF_DDS   138816   // u16[DPER*1024]         30720
#define SMEM_MAIN 169536

// ---------------- device scratch ----------------
__device__ int g_dfill[S_DEN];
__device__ int g_drow[S_DEN + 1];
__device__ uint2 g_dedge[E_DEN];
__device__ unsigned short g_dout[E_DEN];
__device__ int g_dscut[5];
__device__ int g_decut[5];

__device__ int g_nfill[NB * S_NUM];
__device__ int g_nrow[NB * (S_NUM + 1)];
__device__ uint2 g_nedge[NB * E_NUM];
__device__ unsigned short g_nout[NB * E_NUM];
__device__ int g_nscut[NB * 5];
__device__ int g_necut[NB * 5];

__device__ float g_objd[NB];
__device__ float g_objn[NB];

__device__ float g_xexp[(size_t)NB * NT * ND];

// ---------------- cluster / async primitives ----------------
__device__ __forceinline__ unsigned cluster_rank() {
    unsigned r;
    asm("mov.u32 %0, %%cluster_ctarank;" : "=r"(r));
    return r;
}
__device__ __forceinline__ void cluster_sync() {
    asm volatile("barrier.cluster.arrive.aligned;" ::: "memory");
    asm volatile("barrier.cluster.wait.aligned;" ::: "memory");
}
__device__ __forceinline__ unsigned mapa_addr(const void* p, int rank) {
    unsigned local = (unsigned)__cvta_generic_to_shared(p);
    unsigned remote;
    asm("mapa.shared::cluster.u32 %0, %1, %2;" : "=r"(remote) : "r"(local), "r"(rank));
    return remote;
}
__device__ __forceinline__ void stc_f32(unsigned addr, float v) {
    asm volatile("st.shared::cluster.f32 [%0], %1;" :: "r"(addr), "f"(v) : "memory");
}
__device__ __forceinline__ void cpa16(void* dst, const void* src) {
    unsigned d = (unsigned)__cvta_generic_to_shared(dst);
    asm volatile("cp.async.cg.shared.global [%0], [%1], 16;" :: "r"(d), "l"(src));
}

// ---------------- preprocessing ----------------
__global__ void k_exp(const float* __restrict__ x) {
    size_t i = (size_t)blockIdx.x * blockDim.x + threadIdx.x;
    float4 v = __ldg(((const float4*)x) + i);
    float4 o;
    o.x = __expf(fminf(fmaxf(v.x, -30.f), 30.f));
    o.y = __expf(fminf(fmaxf(v.y, -30.f), 30.f));
    o.z = __expf(fminf(fmaxf(v.z, -30.f), 30.f));
    o.w = __expf(fminf(fmaxf(v.w, -30.f), 30.f));
    ((float4*)g_xexp)[i] = o;
}

// block 0: den zero+hist+scan+cuts ; blocks 1..32: num per-b zero+hist+scan+cuts
__global__ void __launch_bounds__(1024) k_graph(const int* __restrict__ de_out,
                                                const int* __restrict__ ne_out) {
    __shared__ int cnt[S_DEN];
    __shared__ int pfx[1024];
    int tid = threadIdx.x;
    if (blockIdx.x == 0) {
        for (int s = tid; s < S_DEN; s += 1024) { cnt[s] = 0; g_dfill[s] = 0; }
        __syncthreads();
        for (int j = tid; j < E_DEN; j += 1024) atomicAdd(&cnt[__ldg(de_out + j)], 1);
        __syncthreads();
        int i0 = 2 * tid, i1 = 2 * tid + 1;
        int c0 = (i0 < S_DEN) ? cnt[i0] : 0;
        int c1 = (i1 < S_DEN) ? cnt[i1] : 0;
        int part = c0 + c1;
        pfx[tid] = part;
        __syncthreads();
        for (int off = 1; off < 1024; off <<= 1) {
            int v = pfx[tid];
            if (tid >= off) v += pfx[tid - off];
            __syncthreads();
            pfx[tid] = v;
            __syncthreads();
        }
        int base = pfx[tid] - part;
        if (i0 <= S_DEN) g_drow[i0] = base;
        if (i1 <= S_DEN) g_drow[i1] = base + c0;
        if (tid == 0) g_drow[S_DEN] = E_DEN;
        __syncthreads();
        for (int s = tid; s < S_DEN; s += 1024) {
            int r = g_drow[s];
            int rp = (s == 0) ? -1 : g_drow[s - 1];
            #pragma unroll
            for (int k = 1; k < 4; k++) {
                int target = k * (E_DEN / 4);
                if (r >= target && rp < target) { g_dscut[k] = s; g_decut[k] = r; }
            }
        }
        if (tid == 0) { g_dscut[0] = 0; g_decut[0] = 0; g_dscut[4] = S_DEN; g_decut[4] = E_DEN; }
    } else {
        int b = blockIdx.x - 1;
        if (tid < S_NUM) { cnt[tid] = 0; g_nfill[b * S_NUM + tid] = 0; }
        __syncthreads();
        for (int j = tid; j < E_NUM; j += 1024)
            atomicAdd(&cnt[__ldg(ne_out + (size_t)b * E_NUM + j)], 1);
        __syncthreads();
        if (tid < S_NUM) pfx[tid] = cnt[tid];
        __syncthreads();
        for (int off = 1; off < S_NUM; off <<= 1) {
            int v = 0;
            if (tid < S_NUM) { v = pfx[tid]; if (tid >= off) v += pfx[tid - off]; }
            __syncthreads();
            if (tid < S_NUM) pfx[tid] = v;
            __syncthreads();
        }
        if (tid < S_NUM) {
            int excl = pfx[tid] - cnt[tid];
            g_nrow[b * (S_NUM + 1) + tid] = excl;
            if (tid == S_NUM - 1) g_nrow[b * (S_NUM + 1) + S_NUM] = E_NUM;
            #pragma unroll
            for (int k = 1; k < 4; k++) {
                int target = k * (E_NUM / 4);
                int exclp = (tid == 0) ? -1 : (pfx[tid - 1] - cnt[tid - 1]);
                if (excl >= target && exclp < target) {
                    g_nscut[b * 5 + k] = tid;
                    g_necut[b * 5 + k] = excl;
                }
            }
            if (tid == 0) {
                g_nscut[b * 5] = 0; g_necut[b * 5] = 0;
                g_nscut[b * 5 + 4] = S_NUM; g_necut[b * 5 + 4] = E_NUM;
            }
        }
    }
}

__global__ void k_scatter(const int* __restrict__ de_in, const int* __restrict__ de_out,
                          const int* __restrict__ de_pdf, const float* __restrict__ de_prob,
                          const int* __restrict__ ne_in, const int* __restrict__ ne_out,
                          const int* __restrict__ ne_pdf, const float* __restrict__ ne_prob) {
    int i = blockIdx.x * blockDim.x + threadIdx.x;
    if (i < E_DEN) {
        int out = de_out[i];
        int p = atomicAdd(&g_dfill[out], 1);
        int pos = g_drow[out] + p;
        unsigned flag = (pos + 1 == g_drow[out + 1]) ? 1u : 0u;
        unsigned pack = (unsigned)de_in[i] | ((unsigned)de_pdf[i] << 11) | (flag << 22);
        g_dedge[pos] = make_uint2(pack, __float_as_uint(de_prob[i]));
        g_dout[pos] = (unsigned short)out;
    }
    if (i < NB * E_NUM) {
        int b = i >> 11;
        int out = ne_out[i];
        int p = atomicAdd(&g_nfill[b * S_NUM + out], 1);
        int pos = g_nrow[b * (S_NUM + 1) + out] + p;
        unsigned flag = (pos + 1 == g_nrow[b * (S_NUM + 1) + out + 1]) ? 1u : 0u;
        unsigned pack = (unsigned)ne_in[i] | ((unsigned)ne_pdf[i] << 11) | (flag << 22);
        g_nedge[b * E_NUM + pos] = make_uint2(pack, __float_as_uint(ne_prob[i]));
        g_nout[b * E_NUM + pos] = (unsigned short)out;
    }
}

// ---------------- main recursion: 1 cluster (4 CTAs) per utterance ----------------
__global__ void __cluster_dims__(4, 1, 1) __launch_bounds__(1024, 1)
k_main(const int* __restrict__ xlen,
       const float* __restrict__ dleaky, const float* __restrict__ dfinal,
       const float* __restrict__ nleaky, const float* __restrict__ nfinal) {
    extern __shared__ char sm[];
    float* AD   = (float*)(sm + OFF_AD);      // [2][S_DEN]
    float* CLD  = (float*)(sm + OFF_CLD);
    float* XT   = (float*)(sm + OFF_XT);      // [2][ND]
    float* AN   = (float*)(sm + OFF_AN);      // [2][S_NUM]
    float* CLN  = (float*)(sm + OFF_CLN);
    float* AW   = (float*)(sm + OFF_AW);
    float* AWN  = (float*)(sm + OFF_AWN);
    uint2* NE   = (uint2*)(sm + OFF_NE);
    unsigned short* NDST = (unsigned short*)(sm + OFF_ND);
    float* SRD  = (float*)(sm + OFF_SRD);
    float* SRN  = (float*)(sm + OFF_SRN);
    float* MAILD = (float*)(sm + OFF_MAILD);  // [2][4]
    float* MAILN = (float*)(sm + OFF_MAILN);  // [2][4]
    float* DPR  = (float*)(sm + OFF_DPR);     // [DPER*1024]
    unsigned short* DDS = (unsigned short*)(sm + OFF_DDS);

    const int rank = (int)cluster_rank();
    const int b = (int)(blockIdx.x >> 2);
    const int tid = threadIdx.x;

    // ---- init state ----
    for (int s = tid; s < S_DEN; s += 1024) {
        float c = 1e-5f * __ldg(dleaky + s);
        CLD[s] = c;
        AD[s] = c + (s == 0 ? 1.0f : 0.0f);
        AW[s] = 0.0f;
    }
    if (tid < S_NUM) {
        float c = 1e-20f * __ldg(nleaky + b * S_NUM + tid);
        CLN[tid] = c;
        AN[tid] = c + (tid == 0 ? 1.0f : 0.0f);
        AWN[tid] = 0.0f;
    }

    const int de0 = g_decut[rank], de1 = g_decut[rank + 1];
    const int ds0 = g_dscut[rank], ds1 = g_dscut[rank + 1];
    const int ne0 = g_necut[b * 5 + rank], ne1 = g_necut[b * 5 + rank + 1];
    const int ns0 = g_nscut[b * 5 + rank], ns1 = g_nscut[b * 5 + rank + 1];

    // ---- stage den edges: pack words -> regs, prob/dest -> smem planes ----
    const int dn = de1 - de0;
    const unsigned short dl = __ldg(&g_dout[de1 - 1]);
    unsigned epack[DPER];
    #pragma unroll
    for (int k = 0; k < DPER; k++) {
        int j = tid * DPER + k;
        if (j < dn) {
            uint2 w = __ldg(&g_dedge[de0 + j]);
            epack[k] = w.x;
            DPR[k * 1024 + tid] = __uint_as_float(w.y);
            DDS[k * 1024 + tid] = __ldg(&g_dout[de0 + j]);
        } else {
            epack[k] = 0u;
            DPR[k * 1024 + tid] = 0.0f;
            DDS[k * 1024 + tid] = dl;
        }
    }
    // ---- stage num edges ----
    const int nn = ne1 - ne0;
    const unsigned short nl = __ldg(&g_nout[(size_t)b * E_NUM + ne1 - 1]);
    #pragma unroll
    for (int k = 0; k < NPER; k++) {
        int j = tid * NPER + k;
        if (j < nn) {
            NE[k * 1024 + tid] = __ldg(&g_nedge[(size_t)b * E_NUM + ne0 + j]);
            NDST[k * 1024 + tid] = __ldg(&g_nout[(size_t)b * E_NUM + ne0 + j]);
        } else {
            NE[k * 1024 + tid] = make_uint2(0u, 0u);
            NDST[k * 1024 + tid] = nl;
        }
    }

    unsigned adr[4], anr[4], mdr[4], mnr[4];
    #pragma unroll
    for (int k = 0; k < 4; k++) {
        adr[k] = mapa_addr(AD, k);
        anr[k] = mapa_addr(AN, k);
        mdr[k] = mapa_addr(MAILD, k);
        mnr[k] = mapa_addr(MAILN, k);
    }

    const int len = xlen[b];
    const float* xe = g_xexp + (size_t)b * NT * ND;

    // frame 0 -> XT[0]
    if (tid < 512) cpa16(XT + tid * 4, xe + tid * 4);
    asm volatile("cp.async.commit_group;" ::: "memory");
    asm volatile("cp.async.wait_group 0;" ::: "memory");
    __syncthreads();
    cluster_sync();

    float lzd = 0.0f, lzn = 0.0f;
    const int lane = tid & 31, wid = tid >> 5;

    for (int t = 0; t < len; ++t) {
        const int buf = t & 1, nb = buf ^ 1;

        if (t + 1 < len && tid < 512)
            cpa16(XT + nb * ND + tid * 4, xe + (size_t)(t + 1) * ND + tid * 4);
        asm volatile("cp.async.commit_group;" ::: "memory");

        const float* ab  = AD + buf * S_DEN;
        const float* xtb = XT + buf * ND;
        const float* anb = AN + buf * S_NUM;

        // ---- den edges (pack in regs, prob conflict-free LDS) ----
        float acc = 0.0f, ssum = 0.0f;
        #pragma unroll
        for (int k = 0; k < DPER; k++) {
            const unsigned w = epack[k];
            float p = DPR[k * 1024 + tid];
            float av = ab[w & 2047u];
            float xv = xtb[(w >> 11) & 2047u];
            acc = fmaf(av * xv, p, acc);
            if (w & (1u << 22)) {
                atomicAdd(&AW[DDS[k * 1024 + tid]], acc);
                ssum += acc;
                acc = 0.0f;
            }
        }
        if (acc != 0.0f) { atomicAdd(&AW[DDS[(DPER - 1) * 1024 + tid]], acc); ssum += acc; }

        // ---- num edges ----
        float nacc = 0.0f, nsum = 0.0f;
        #pragma unroll
        for (int k = 0; k < NPER; k++) {
            uint2 w = NE[k * 1024 + tid];
            float av = anb[w.x & 2047u];
            float xv = xtb[(w.x >> 11) & 2047u];
            nacc = fmaf(av * xv, __uint_as_float(w.y), nacc);
            if (w.x & (1u << 22)) {
                atomicAdd(&AWN[NDST[k * 1024 + tid]], nacc);
                nsum += nacc;
                nacc = 0.0f;
            }
        }
        if (nacc != 0.0f) { atomicAdd(&AWN[NDST[(NPER - 1) * 1024 + tid]], nacc); nsum += nacc; }

        // ---- two-level reduction (plain stores, no smem atomics) ----
        #pragma unroll
        for (int o = 16; o; o >>= 1) {
            ssum += __shfl_xor_sync(0xffffffffu, ssum, o);
            nsum += __shfl_xor_sync(0xffffffffu, nsum, o);
        }
        if (lane == 0) { SRD[wid] = ssum; SRN[wid] = nsum; }
        __syncthreads();   // AW/AWN/SRD/SRN complete

        if (tid < 32) {
            float v = SRD[tid];
            #pragma unroll
            for (int o = 16; o; o >>= 1) v += __shfl_xor_sync(0xffffffffu, v, o);
            if (tid == 0) {
                #pragma unroll
                for (int k = 0; k < 4; k++)
                    stc_f32(mdr[k] + 4u * (unsigned)(buf * 4 + rank), v);
            }
        } else if (tid < 64) {
            float v = SRN[lane];
            #pragma unroll
            for (int o = 16; o; o >>= 1) v += __shfl_xor_sync(0xffffffffu, v, o);
            if (lane == 0) {
                #pragma unroll
                for (int k = 0; k < 4; k++)
                    stc_f32(mnr[k] + 4u * (unsigned)(buf * 4 + rank), v);
            }
        }

        // ---- broadcast RAW anew slices into alpha[nb] of all 4 ranks ----
        for (int s = ds0 + tid; s < ds1; s += 1024) {
            float v = AW[s];
            AW[s] = 0.0f;
            unsigned off = 4u * (unsigned)(nb * S_DEN + s);
            #pragma unroll
            for (int k = 0; k < 4; k++) stc_f32(adr[k] + off, v);
        }
        for (int s = ns0 + tid; s < ns1; s += 1024) {
            float v = AWN[s];
            AWN[s] = 0.0f;
            unsigned off = 4u * (unsigned)(nb * S_NUM + s);
            #pragma unroll
            for (int k = 0; k < 4; k++) stc_f32(anr[k] + off, v);
        }
        cluster_sync();

        // ---- everyone computes asum locally; normalize full local replica ----
        float asd = MAILD[buf * 4 + 0] + MAILD[buf * 4 + 1] + MAILD[buf * 4 + 2] + MAILD[buf * 4 + 3];
        float asn = MAILN[buf * 4 + 0] + MAILN[buf * 4 + 1] + MAILN[buf * 4 + 2] + MAILN[buf * 4 + 3];
        float invd = 1.0f / asd;
        float invn = 1.0f / asn;
        if (rank == 0 && tid == 0) { lzd += __logf(asd); lzn += __logf(asn); }

        float* adn = AD + nb * S_DEN;
        float* ann = AN + nb * S_NUM;
        for (int s = tid; s < S_DEN; s += 1024) adn[s] = fmaf(adn[s], invd, CLD[s]);
        if (tid < S_NUM) ann[tid] = fmaf(ann[tid], invn, CLN[tid]);

        asm volatile("cp.async.wait_group 0;" ::: "memory");
        __syncthreads();   // normalize + XT[nb] visible
    }

    // ---- final: objf_b = logz + log(sum(alpha * final)) on rank 0 ----
    if (rank == 0) {
        const int fb = len & 1;
        float fd = 0.0f, fn = 0.0f;
        for (int s = tid; s < S_DEN; s += 1024) fd += AD[fb * S_DEN + s] * __ldg(dfinal + s);
        for (int s = tid; s < S_NUM; s += 1024) fn += AN[fb * S_NUM + s] * __ldg(nfinal + b * S_NUM + s);
        #pragma unroll
        for (int o = 16; o; o >>= 1) {
            fd += __shfl_xor_sync(0xffffffffu, fd, o);
            fn += __shfl_xor_sync(0xffffffffu, fn, o);
        }
        if (lane == 0) { SRD[wid] = fd; SRN[wid] = fn; }
        __syncthreads();
        if (tid < 32) {
            float v = SRD[tid];
            #pragma unroll
            for (int o = 16; o; o >>= 1) v += __shfl_xor_sync(0xffffffffu, v, o);
            if (tid == 0) SRD[0] = v;
        } else if (tid < 64) {
            float v = SRN[lane];
            #pragma unroll
            for (int o = 16; o; o >>= 1) v += __shfl_xor_sync(0xffffffffu, v, o);
            if (lane == 0) SRN[0] = v;
        }
        __syncthreads();
        if (tid == 0) {
            g_objd[b] = lzd + logf(SRD[0]);
            g_objn[b] = lzn + logf(SRN[0]);
        }
    }
}

__global__ void k_final(const int* __restrict__ xlen, float* __restrict__ out) {
    int tid = threadIdx.x;  // 32 threads
    float d = g_objd[tid];
    float n = g_objn[tid];
    float l = (float)xlen[tid];
    #pragma unroll
    for (int o = 16; o; o >>= 1) {
        d += __shfl_xor_sync(0xffffffffu, d, o);
        n += __shfl_xor_sync(0xffffffffu, n, o);
        l += __shfl_xor_sync(0xffffffffu, l, o);
    }
    if (tid == 0) out[0] = -(n - d) / l;
}

// ---------------- launch ----------------
extern "C" void kernel_launch(void* const* d_in, const int* in_sizes, int n_in,
                              void* d_out, int out_size) {
    const float* x = (const float*)d_in[0];
    const int* xlen = (const int*)d_in[1];
    const int* de_in = (const int*)d_in[2];
    const int* de_out = (const int*)d_in[3];
    const int* de_pdf = (const int*)d_in[4];
    const float* de_prob = (const float*)d_in[5];
    const float* dleaky = (const float*)d_in[6];
    const float* dfinal = (const float*)d_in[7];
    const int* ne_in = (const int*)d_in[8];
    const int* ne_out = (const int*)d_in[9];
    const int* ne_pdf = (const int*)d_in[10];
    const float* ne_prob = (const float*)d_in[11];
    const float* nleaky = (const float*)d_in[12];
    const float* nfinal = (const float*)d_in[13];
    float* out = (float*)d_out;

    cudaFuncSetAttribute(k_main, cudaFuncAttributeMaxDynamicSharedMemorySize, SMEM_MAIN);

    k_exp<<<(NB * NT * ND / 4 + 1023) / 1024, 1024>>>(x);                 // launch 0
    k_graph<<<NB + 1, 1024>>>(de_out, ne_out);                            // launch 1
    k_scatter<<<256, 256>>>(de_in, de_out, de_pdf, de_prob,
                            ne_in, ne_out, ne_pdf, ne_prob);              // launch 2
    k_main<<<NB * 4, 1024, SMEM_MAIN>>>(xlen, dleaky, dfinal, nleaky, nfinal); // launch 3 (ncu)
    k_final<<<1, 32>>>(xlen, out);                                        // launch 4
}